// round 10
// baseline (speedup 1.0000x reference)
#include <cuda_runtime.h>
#include <cuda_bf16.h>

#define T_STEPS   300
#define BATCH     2048
#define NPIX      225
#define NOUT      10
#define NTHREADS  288      // 2ch * 12 * 12 conv elements, pool-quad-major
#define SIGW      8        // 8*32 = 256 >= max classes
#define PTILE     32
#define DUMMY_CLS 230
#define ACT_N     232

// ---------------- device scratch (no allocations allowed) ----------------
__device__ int g_periods[BATCH * NPIX];

// =========================================================================
// K1: per-pixel encoder first-spike step k (1-based), 0 if never spikes.
// v <- fma(0.1f, c - v, v); spike v>1; reset v - z*v -> exact +0 for z=1,
// so spikes are exactly {k, 2k, 3k, ...}.
// =========================================================================
__global__ void k_periods(const float* __restrict__ x) {
    int idx = blockIdx.x * blockDim.x + threadIdx.x;
    if (idx >= BATCH * NPIX) return;
    float c = __fmul_rn(x[idx], 10.0f);
    float v = 0.0f;
    int k = 0;
    for (int s = 1; s <= T_STEPS; ++s) {
        v = fmaf(0.1f, __fsub_rn(c, v), v);
        if (v > 1.0f) { k = s; break; }
    }
    g_periods[idx] = k;
}

// =========================================================================
// K2: one CTA per batch element.
// =========================================================================
struct __align__(16) Sm {
    float    wlin[NOUT * 72];
    float    pooled[PTILE][76];
    float    lin_pat[T_STEPS][NOUT];
    float    act[2][ACT_N];
    unsigned sig[T_STEPS][SIGW];
    unsigned hsh[T_STEPS];
    int      pid[T_STEPS];
    int      pat_of[T_STEPS];
    int      rep[T_STEPS];
    int      class_of[301];
    int      period_of[226];
    int      kk[NPIX];
    float    wconv[32];
    float    blin[NOUT];
    float    bconv[2];
    int      nclass, npat;
};  // ~44 KB

__global__ void __launch_bounds__(NTHREADS, 2)
k_forward(const float* __restrict__ conv_w, const float* __restrict__ conv_b,
          const float* __restrict__ lin_w,  const float* __restrict__ lin_b,
          float* __restrict__ out) {
    __shared__ Sm sm;
    const int tid = threadIdx.x;
    const int b   = blockIdx.x;

    // ---------------- phase 0: loads + zeroing (pure f32 everywhere) -------
    for (int i = tid; i < NOUT * 72; i += NTHREADS) sm.wlin[i] = lin_w[i];
    if (tid < 32)   sm.wconv[tid] = conv_w[tid];
    if (tid < NOUT) sm.blin[tid]  = lin_b[tid];
    if (tid < 2)    sm.bconv[tid] = conv_b[tid];
    if (tid < NPIX) sm.kk[tid]    = g_periods[b * NPIX + tid];
    for (int i = tid; i < 301; i += NTHREADS) sm.class_of[i] = 0;
    for (int i = tid; i < T_STEPS * SIGW; i += NTHREADS)
        ((unsigned*)sm.sig)[i] = 0u;
    for (int i = tid; i < 2 * ACT_N; i += NTHREADS)
        ((float*)sm.act)[i] = 0.0f;
    __syncthreads();

    // ---------------- phase 1: mark present periods ----------------
    if (tid < NPIX) {
        int k = sm.kk[tid];
        if (k > 0) sm.class_of[k] = 1;   // benign same-value race
    }
    __syncthreads();

    // ---------------- phase 2: build class list ----------------
    if (tid == 0) {
        int n = 0;
        for (int k = 1; k <= 300; ++k) {
            if (sm.class_of[k]) { sm.class_of[k] = n; sm.period_of[n] = k; n++; }
            else                  sm.class_of[k] = -1;
        }
        sm.nclass = n;
    }
    __syncthreads();
    const int nclass = sm.nclass;

    // ---------------- per-thread conv-tap geometry ----------------
    const int pb = tid >> 2, q = tid & 3;
    const int o  = pb / 36;
    const int rem = pb % 36;
    const int pi = rem / 6, pj = rem % 6;
    const int ci = 2 * pi + (q >> 1);
    const int cj = 2 * pj + (q & 1);
    const float bias_t = sm.bconv[o];
    float wreg[16];
    int   creg[16];
    #pragma unroll
    for (int kh = 0; kh < 4; ++kh)
        #pragma unroll
        for (int kw = 0; kw < 4; ++kw) {
            int t4 = kh * 4 + kw;
            int k  = sm.kk[(ci + kh) * 15 + (cj + kw)];
            creg[t4] = (k > 0) ? sm.class_of[k] : DUMMY_CLS;
            wreg[t4] = sm.wconv[o * 16 + t4];
        }

    // ---------------- phase 3: class-activity signatures ----------------
    for (int c = tid; c < nclass; c += NTHREADS) {
        int k = sm.period_of[c];
        unsigned m = 1u << (c & 31);
        int w = c >> 5;
        for (int s = k - 1; s < T_STEPS; s += k)
            atomicOr(&sm.sig[s][w], m);
    }
    __syncthreads();

    for (int t = tid; t < T_STEPS; t += NTHREADS) {
        unsigned h = 0;
        #pragma unroll
        for (int j = 0; j < SIGW; ++j)
            h = (h ^ sm.sig[t][j]) * 2654435761u;
        sm.hsh[t] = h;
    }
    __syncthreads();

    // ---------------- phase 4: dedup steps into patterns ----------------
    for (int t = tid; t < T_STEPS; t += NTHREADS) {
        unsigned h = sm.hsh[t];
        int f = t;
        for (int t2 = 0; t2 < t; ++t2) {
            if (sm.hsh[t2] == h) {
                bool eq = true;
                #pragma unroll
                for (int j = 0; j < SIGW; ++j)
                    eq = eq && (sm.sig[t2][j] == sm.sig[t][j]);
                if (eq) { f = t2; break; }
            }
        }
        sm.pid[t] = f;
    }
    __syncthreads();

    if (tid == 0) {
        int n = 0;
        for (int t = 0; t < T_STEPS; ++t) {
            int p = sm.pid[t];
            if (p == t) { sm.pat_of[t] = n; sm.rep[n] = t; n++; }
            else          sm.pat_of[t] = sm.pat_of[p];
        }
        sm.npat = n;
    }
    __syncthreads();
    const int npat = sm.npat;

    // ---------------- phase 5: per-pattern conv + pool + linear ----------------
    for (int p0 = 0; p0 < npat; p0 += PTILE) {
        int ntile = npat - p0; if (ntile > PTILE) ntile = PTILE;

        for (int pp = 0; pp < ntile; ++pp) {
            int p = p0 + pp;
            int buf = pp & 1;
            if (tid < nclass) {
                int tr = sm.rep[p];
                unsigned wv = sm.sig[tr][tid >> 5];
                sm.act[buf][tid] = (float)((wv >> (tid & 31)) & 1u);
            }
            __syncthreads();

            // conv: cudnn implicit-gemm — taps ascending (kh,kw), serial FMA
            // chain from 0; products w*act exact (act in {0,1}); bias last.
            float a = 0.0f;
            #pragma unroll
            for (int t4 = 0; t4 < 16; ++t4)
                a = fmaf(wreg[t4], sm.act[buf][creg[t4]], a);
            a = __fadd_rn(a, bias_t);

            float m01 = fmaxf(a, __shfl_xor_sync(0xFFFFFFFFu, a, 1));
            float m   = fmaxf(m01, __shfl_xor_sync(0xFFFFFFFFu, m01, 2));
            if (q == 0) sm.pooled[pp][pb] = m;   // pure f32
        }
        __syncthreads();

        // Linear: cublas sgemm_32x32_sliced1x4_nt tree.
        // 4 k-sliced accumulators P[s] over k ≡ s (mod 4), 18 serial FMAs each
        // (ascending within slice, acc from 0); epilogue stride-halving:
        // P0+=P2, P1+=P3, P0+=P1  =>  (P0+P2)+(P1+P3); bias added last.
        for (int idx = tid; idx < ntile * NOUT; idx += NTHREADS) {
            int oo = idx % NOUT;
            int pp = idx / NOUT;
            const float* pv = sm.pooled[pp];
            const float* wv = &sm.wlin[oo * 72];
            float P0 = 0.0f, P1 = 0.0f, P2 = 0.0f, P3 = 0.0f;
            #pragma unroll
            for (int j = 0; j < 18; ++j) {
                int k = j * 4;
                P0 = fmaf(pv[k + 0], wv[k + 0], P0);
                P1 = fmaf(pv[k + 1], wv[k + 1], P1);
                P2 = fmaf(pv[k + 2], wv[k + 2], P2);
                P3 = fmaf(pv[k + 3], wv[k + 3], P3);
            }
            float a02 = __fadd_rn(P0, P2);
            float a13 = __fadd_rn(P1, P3);
            float acc = __fadd_rn(a02, a13);
            sm.lin_pat[p0 + pp][oo] = __fadd_rn(acc, sm.blin[oo]);
        }
        __syncthreads();
    }

    // ---------------- phase 6: fused sequential decoder ----------------
    if (tid < NOUT) {
        float v = 0.0f, cur = 0.0f, ss = 0.0f;
        float* __restrict__ mem = out + BATCH * NOUT;
        float* __restrict__ spk = mem + (long)T_STEPS * BATCH * NOUT;
        const int base = b * NOUT + tid;
        for (int t = 0; t < T_STEPS; ++t) {
            float lv = sm.lin_pat[sm.pat_of[t]][tid];
            float vd = fmaf(0.1f, __fsub_rn(cur, v), v);
            float id = fmaf(-0.2f, cur, cur);
            bool  sp = vd > 1.0f;
            v   = sp ? 0.0f : vd;
            cur = __fadd_rn(id, lv);
            float spf = sp ? 1.0f : 0.0f;
            ss += spf;
            long ofs = (long)t * (BATCH * NOUT) + base;
            mem[ofs] = v;
            spk[ofs] = spf;
        }
        out[base] = ss;
    }
}

extern "C" void kernel_launch(void* const* d_in, const int* in_sizes, int n_in,
                              void* d_out, int out_size) {
    const float* x      = (const float*)d_in[0];
    const float* conv_w = (const float*)d_in[1];
    const float* conv_b = (const float*)d_in[2];
    const float* lin_w  = (const float*)d_in[3];
    const float* lin_b  = (const float*)d_in[4];
    float* out = (float*)d_out;

    k_periods<<<(BATCH * NPIX + 255) / 256, 256>>>(x);
    k_forward<<<BATCH, NTHREADS>>>(conv_w, conv_b, lin_w, lin_b, out);
}

// round 11
// speedup vs baseline: 1.5092x; 1.5092x over previous
#include <cuda_runtime.h>
#include <cuda_bf16.h>

#define T_STEPS   300
#define BATCH     2048
#define NPIX      225
#define NOUT      10
#define NTHREADS  288      // 2ch * 12 * 12 conv elements, pool-quad-major
#define SIGW      8        // 8*32 = 256 >= max classes
#define PTILE     32

// ---------------- device scratch (no allocations allowed) ----------------
__device__ int g_periods[BATCH * NPIX];

// =========================================================================
// K1: per-pixel encoder first-spike step k (1-based), 0 if never spikes.
// v <- fma(0.1f, c - v, v); spike v>1; reset v - z*v -> exact +0 for z=1,
// so spikes are exactly {k, 2k, 3k, ...}.
// =========================================================================
__global__ void k_periods(const float* __restrict__ x) {
    int idx = blockIdx.x * blockDim.x + threadIdx.x;
    if (idx >= BATCH * NPIX) return;
    float c = __fmul_rn(x[idx], 10.0f);
    float v = 0.0f;
    int k = 0;
    for (int s = 1; s <= T_STEPS; ++s) {
        v = fmaf(0.1f, __fsub_rn(c, v), v);
        if (v > 1.0f) { k = s; break; }
    }
    g_periods[idx] = k;
}

// =========================================================================
// K2: one CTA per batch element.
// =========================================================================
struct __align__(16) Sm {
    // order matters: keep sig 16B-aligned (2880+9728+12000 = 24608 = 16*1538)
    float    wlin[NOUT * 72];          // 2880 B
    float    pooled[PTILE][76];        // 9728 B
    float    lin_pat[T_STEPS][NOUT];   // 12000 B
    unsigned sig[T_STEPS][SIGW];       // 9600 B
    unsigned hsh[T_STEPS];
    int      pid[T_STEPS];
    int      pat_of[T_STEPS];
    int      rep[T_STEPS];
    int      class_of[301];
    int      period_of[226];
    int      kk[NPIX];
    float    wconv[32];
    float    blin[NOUT];
    float    bconv[2];
    int      nclass, npat;
};  // ~42.6 KB

__global__ void __launch_bounds__(NTHREADS, 3)
k_forward(const float* __restrict__ conv_w, const float* __restrict__ conv_b,
          const float* __restrict__ lin_w,  const float* __restrict__ lin_b,
          float* __restrict__ out) {
    __shared__ Sm sm;
    const int tid = threadIdx.x;
    const int b   = blockIdx.x;

    // ---------------- phase 0: loads ----------------
    for (int i = tid; i < NOUT * 72; i += NTHREADS) sm.wlin[i] = lin_w[i];
    if (tid < 32)   sm.wconv[tid] = conv_w[tid];
    if (tid < NOUT) sm.blin[tid]  = lin_b[tid];
    if (tid < 2)    sm.bconv[tid] = conv_b[tid];
    if (tid < NPIX) sm.kk[tid]    = g_periods[b * NPIX + tid];
    for (int i = tid; i < 301; i += NTHREADS) sm.class_of[i] = 0;
    __syncthreads();

    // ---------------- phase 1: mark present periods ----------------
    if (tid < NPIX) {
        int k = sm.kk[tid];
        if (k > 0) sm.class_of[k] = 1;   // benign same-value race
    }
    __syncthreads();

    // ---------------- phase 2: build class list ----------------
    if (tid == 0) {
        int n = 0;
        for (int k = 1; k <= 300; ++k) {
            if (sm.class_of[k]) { sm.class_of[k] = n; sm.period_of[n] = k; n++; }
            else                  sm.class_of[k] = -1;
        }
        sm.nclass = n;
    }
    __syncthreads();
    const int nclass = sm.nclass;

    // ---------------- per-thread conv-tap geometry ----------------
    const int pb = tid >> 2, q = tid & 3;
    const int o  = pb / 36;
    const int rem = pb % 36;
    const int pi = rem / 6, pj = rem % 6;
    const int ci = 2 * pi + (q >> 1);
    const int cj = 2 * pj + (q & 1);
    const float bias_t = sm.bconv[o];
    float    wreg[16];
    unsigned mask[16];         // bit within sig word (0 => tap never active)
    unsigned wsel = 0;         // bit t4: word index LSB (for nclass<=64 path)
    unsigned woffpack[4] = {0, 0, 0, 0};   // per-tap word byte offsets (generic)
    #pragma unroll
    for (int kh = 0; kh < 4; ++kh)
        #pragma unroll
        for (int kw = 0; kw < 4; ++kw) {
            int t4 = kh * 4 + kw;
            int k  = sm.kk[(ci + kh) * 15 + (cj + kw)];
            int cls = (k > 0) ? sm.class_of[k] : -1;
            wreg[t4] = sm.wconv[o * 16 + t4];
            if (cls >= 0) {
                mask[t4] = 1u << (cls & 31);
                int wo = cls >> 5;
                wsel |= (unsigned)(wo & 1) << t4;
                woffpack[t4 >> 2] |= (unsigned)(wo << 2) << ((t4 & 3) << 3);
            } else {
                mask[t4] = 0u;
            }
        }

    // ---------------- phase 3: class-activity signatures (no atomics) ------
    for (int t = tid; t < T_STEPS; t += NTHREADS) {
        int tp1 = t + 1;
        #pragma unroll
        for (int w = 0; w < SIGW; ++w) {
            unsigned m = 0;
            int c0 = w * 32;
            int cn = nclass - c0; if (cn > 32) cn = 32;
            for (int j = 0; j < cn; ++j)
                if (tp1 % sm.period_of[c0 + j] == 0) m |= 1u << j;
            sm.sig[t][w] = m;
        }
    }
    __syncthreads();

    for (int t = tid; t < T_STEPS; t += NTHREADS) {
        unsigned h = 0;
        #pragma unroll
        for (int j = 0; j < SIGW; ++j)
            h = (h ^ sm.sig[t][j]) * 2654435761u;
        sm.hsh[t] = h;
    }
    __syncthreads();

    // ---------------- phase 4: dedup steps into patterns ----------------
    for (int t = tid; t < T_STEPS; t += NTHREADS) {
        unsigned h = sm.hsh[t];
        int f = t;
        for (int t2 = 0; t2 < t; ++t2) {
            if (sm.hsh[t2] == h) {
                bool eq = true;
                #pragma unroll
                for (int j = 0; j < SIGW; ++j)
                    eq = eq && (sm.sig[t2][j] == sm.sig[t][j]);
                if (eq) { f = t2; break; }
            }
        }
        sm.pid[t] = f;
    }
    __syncthreads();

    if (tid == 0) {
        int n = 0;
        for (int t = 0; t < T_STEPS; ++t) {
            int p = sm.pid[t];
            if (p == t) { sm.pat_of[t] = n; sm.rep[n] = t; n++; }
            else          sm.pat_of[t] = sm.pat_of[p];
        }
        sm.npat = n;
    }
    __syncthreads();
    const int npat = sm.npat;

    // ---------------- phase 5: per-pattern conv + pool + linear ----------------
    // conv numerics (frozen): taps ascending t4, predicated __fadd_rn chain
    // from 0 == fmaf(w, act∈{0,1}, a) chain; bias last. pool: shfl-max pairs.
    for (int p0 = 0; p0 < npat; p0 += PTILE) {
        int ntile = npat - p0; if (ntile > PTILE) ntile = PTILE;

        if (nclass <= 32) {
            #pragma unroll 2
            for (int pp = 0; pp < ntile; ++pp) {
                int tr = sm.rep[p0 + pp];
                unsigned s0 = sm.sig[tr][0];
                float a = 0.0f;
                #pragma unroll
                for (int t4 = 0; t4 < 16; ++t4)
                    if (s0 & mask[t4]) a = __fadd_rn(a, wreg[t4]);
                a = __fadd_rn(a, bias_t);
                float m01 = fmaxf(a, __shfl_xor_sync(0xFFFFFFFFu, a, 1));
                float m   = fmaxf(m01, __shfl_xor_sync(0xFFFFFFFFu, m01, 2));
                if (q == 0) sm.pooled[pp][pb] = m;
            }
        } else if (nclass <= 64) {
            #pragma unroll 2
            for (int pp = 0; pp < ntile; ++pp) {
                int tr = sm.rep[p0 + pp];
                uint2 s01 = *(const uint2*)&sm.sig[tr][0];
                float a = 0.0f;
                #pragma unroll
                for (int t4 = 0; t4 < 16; ++t4) {
                    unsigned w = ((wsel >> t4) & 1u) ? s01.y : s01.x;
                    if (w & mask[t4]) a = __fadd_rn(a, wreg[t4]);
                }
                a = __fadd_rn(a, bias_t);
                float m01 = fmaxf(a, __shfl_xor_sync(0xFFFFFFFFu, a, 1));
                float m   = fmaxf(m01, __shfl_xor_sync(0xFFFFFFFFu, m01, 2));
                if (q == 0) sm.pooled[pp][pb] = m;
            }
        } else {
            for (int pp = 0; pp < ntile; ++pp) {
                int tr = sm.rep[p0 + pp];
                const char* row = (const char*)&sm.sig[tr][0];
                float a = 0.0f;
                #pragma unroll
                for (int t4 = 0; t4 < 16; ++t4) {
                    unsigned off = (woffpack[t4 >> 2] >> ((t4 & 3) << 3)) & 0xFFu;
                    unsigned w = *(const unsigned*)(row + off);
                    if (w & mask[t4]) a = __fadd_rn(a, wreg[t4]);
                }
                a = __fadd_rn(a, bias_t);
                float m01 = fmaxf(a, __shfl_xor_sync(0xFFFFFFFFu, a, 1));
                float m   = fmaxf(m01, __shfl_xor_sync(0xFFFFFFFFu, m01, 2));
                if (q == 0) sm.pooled[pp][pb] = m;
            }
        }
        __syncthreads();

        // Linear (frozen): cublas sliced1x4 tree — 4 mod-4 partials, 18 serial
        // FMAs each, halving combine (P0+P2)+(P1+P3), bias last.
        for (int idx = tid; idx < ntile * NOUT; idx += NTHREADS) {
            int oo = idx % NOUT;
            int pp = idx / NOUT;
            const float* pv = sm.pooled[pp];
            const float* wv = &sm.wlin[oo * 72];
            float P0 = 0.0f, P1 = 0.0f, P2 = 0.0f, P3 = 0.0f;
            #pragma unroll
            for (int j = 0; j < 18; ++j) {
                int k = j * 4;
                P0 = fmaf(pv[k + 0], wv[k + 0], P0);
                P1 = fmaf(pv[k + 1], wv[k + 1], P1);
                P2 = fmaf(pv[k + 2], wv[k + 2], P2);
                P3 = fmaf(pv[k + 3], wv[k + 3], P3);
            }
            float a02 = __fadd_rn(P0, P2);
            float a13 = __fadd_rn(P1, P3);
            float acc = __fadd_rn(a02, a13);
            sm.lin_pat[p0 + pp][oo] = __fadd_rn(acc, sm.blin[oo]);
        }
        __syncthreads();
    }

    // ---------------- phase 6: fused sequential decoder (frozen) -----------
    if (tid < NOUT) {
        float v = 0.0f, cur = 0.0f, ss = 0.0f;
        float* __restrict__ mem = out + BATCH * NOUT;
        float* __restrict__ spk = mem + (long)T_STEPS * BATCH * NOUT;
        const int base = b * NOUT + tid;
        for (int t = 0; t < T_STEPS; ++t) {
            float lv = sm.lin_pat[sm.pat_of[t]][tid];
            float vd = fmaf(0.1f, __fsub_rn(cur, v), v);
            float id = fmaf(-0.2f, cur, cur);
            bool  sp = vd > 1.0f;
            v   = sp ? 0.0f : vd;
            cur = __fadd_rn(id, lv);
            float spf = sp ? 1.0f : 0.0f;
            ss += spf;
            long ofs = (long)t * (BATCH * NOUT) + base;
            mem[ofs] = v;
            spk[ofs] = spf;
        }
        out[base] = ss;
    }
}

extern "C" void kernel_launch(void* const* d_in, const int* in_sizes, int n_in,
                              void* d_out, int out_size) {
    const float* x      = (const float*)d_in[0];
    const float* conv_w = (const float*)d_in[1];
    const float* conv_b = (const float*)d_in[2];
    const float* lin_w  = (const float*)d_in[3];
    const float* lin_b  = (const float*)d_in[4];
    float* out = (float*)d_out;

    k_periods<<<(BATCH * NPIX + 255) / 256, 256>>>(x);
    k_forward<<<BATCH, NTHREADS>>>(conv_w, conv_b, lin_w, lin_b, out);
}

// round 12
// speedup vs baseline: 1.7045x; 1.1294x over previous
#include <cuda_runtime.h>
#include <cuda_bf16.h>

#define T_STEPS   300
#define BATCH     2048
#define NPIX      225
#define NOUT      10
#define NTHREADS  288      // 2ch * 12 * 12 conv elements, pool-quad-major
#define SIGW      8        // 8*32 = 256 >= max classes
#define PTILE     32

// ---------------- device scratch (no allocations allowed) ----------------
__device__ int g_periods[BATCH * NPIX];

// =========================================================================
// K1: per-pixel encoder first-spike step k (1-based), 0 if never spikes.
// v <- fma(0.1f, c - v, v); spike v>1; reset v - z*v -> exact +0 for z=1,
// so spikes are exactly {k, 2k, 3k, ...}.
// =========================================================================
__global__ void k_periods(const float* __restrict__ x) {
    int idx = blockIdx.x * blockDim.x + threadIdx.x;
    if (idx >= BATCH * NPIX) return;
    float c = __fmul_rn(x[idx], 10.0f);
    float v = 0.0f;
    int k = 0;
    for (int s = 1; s <= T_STEPS; ++s) {
        v = fmaf(0.1f, __fsub_rn(c, v), v);
        if (v > 1.0f) { k = s; break; }
    }
    g_periods[idx] = k;
}

// =========================================================================
// K2: one CTA per batch element.
// =========================================================================
struct __align__(16) Sm {
    float    wlin[NOUT * 72];          // 2880 B
    float    pooled[PTILE][76];        // 9728 B
    float    lin_pat[T_STEPS][NOUT];   // 12000 B
    unsigned sig[T_STEPS][SIGW];       // 9600 B (16B-aligned: 24608 above)
    unsigned hsh[T_STEPS];
    int      pid[T_STEPS];
    int      pat_of[T_STEPS];
    int      rep[T_STEPS];
    int      class_of[301];
    int      period_of[226];
    int      kk[NPIX];
    float    wconv[32];
    float    blin[NOUT];
    float    bconv[2];
    int      nclass, npat;
};  // ~42.6 KB

__global__ void __launch_bounds__(NTHREADS, 4)
k_forward(const float* __restrict__ conv_w, const float* __restrict__ conv_b,
          const float* __restrict__ lin_w,  const float* __restrict__ lin_b,
          float* __restrict__ out) {
    __shared__ Sm sm;
    const int tid = threadIdx.x;
    const int b   = blockIdx.x;

    // ---------------- phase 0: loads ----------------
    for (int i = tid; i < NOUT * 72; i += NTHREADS) sm.wlin[i] = lin_w[i];
    if (tid < 32)   sm.wconv[tid] = conv_w[tid];
    if (tid < NOUT) sm.blin[tid]  = lin_b[tid];
    if (tid < 2)    sm.bconv[tid] = conv_b[tid];
    if (tid < NPIX) sm.kk[tid]    = g_periods[b * NPIX + tid];
    for (int i = tid; i < 301; i += NTHREADS) sm.class_of[i] = 0;
    __syncthreads();

    // ---------------- phase 1: mark present periods ----------------
    if (tid < NPIX) {
        int k = sm.kk[tid];
        if (k > 0) sm.class_of[k] = 1;   // benign same-value race
    }
    __syncthreads();

    // ---------------- phase 2: build class list ----------------
    if (tid == 0) {
        int n = 0;
        for (int k = 1; k <= 300; ++k) {
            if (sm.class_of[k]) { sm.class_of[k] = n; sm.period_of[n] = k; n++; }
            else                  sm.class_of[k] = -1;
        }
        sm.nclass = n;
    }
    __syncthreads();
    const int nclass = sm.nclass;

    // ---------------- per-thread conv-tap geometry ----------------
    const int pb = tid >> 2, q = tid & 3;
    const int o  = pb / 36;
    const int rem = pb % 36;
    const int pi = rem / 6, pj = rem % 6;
    const int ci = 2 * pi + (q >> 1);
    const int cj = 2 * pj + (q & 1);
    const float bias_t = sm.bconv[o];
    float    wreg[16];
    unsigned mask[16];         // bit within sig word (0 => tap never active)
    unsigned wsel = 0;         // bit t4: word index LSB (for nclass<=64 path)
    unsigned woffpack[4] = {0, 0, 0, 0};   // per-tap word byte offsets (generic)
    #pragma unroll
    for (int kh = 0; kh < 4; ++kh)
        #pragma unroll
        for (int kw = 0; kw < 4; ++kw) {
            int t4 = kh * 4 + kw;
            int k  = sm.kk[(ci + kh) * 15 + (cj + kw)];
            int cls = (k > 0) ? sm.class_of[k] : -1;
            wreg[t4] = sm.wconv[o * 16 + t4];
            if (cls >= 0) {
                mask[t4] = 1u << (cls & 31);
                int wo = cls >> 5;
                wsel |= (unsigned)(wo & 1) << t4;
                woffpack[t4 >> 2] |= (unsigned)(wo << 2) << ((t4 & 3) << 3);
            } else {
                mask[t4] = 0u;
            }
        }

    // ---------------- phase 3: class-activity signatures (no atomics) ------
    for (int t = tid; t < T_STEPS; t += NTHREADS) {
        int tp1 = t + 1;
        #pragma unroll
        for (int w = 0; w < SIGW; ++w) {
            unsigned m = 0;
            int c0 = w * 32;
            int cn = nclass - c0; if (cn > 32) cn = 32;
            for (int j = 0; j < cn; ++j)
                if (tp1 % sm.period_of[c0 + j] == 0) m |= 1u << j;
            sm.sig[t][w] = m;
        }
    }
    __syncthreads();

    for (int t = tid; t < T_STEPS; t += NTHREADS) {
        unsigned h = 0;
        #pragma unroll
        for (int j = 0; j < SIGW; ++j)
            h = (h ^ sm.sig[t][j]) * 2654435761u;
        sm.hsh[t] = h;
    }
    __syncthreads();

    // ---------------- phase 4: dedup steps into patterns ----------------
    for (int t = tid; t < T_STEPS; t += NTHREADS) {
        unsigned h = sm.hsh[t];
        int f = t;
        for (int t2 = 0; t2 < t; ++t2) {
            if (sm.hsh[t2] == h) {
                bool eq = true;
                #pragma unroll
                for (int j = 0; j < SIGW; ++j)
                    eq = eq && (sm.sig[t2][j] == sm.sig[t][j]);
                if (eq) { f = t2; break; }
            }
        }
        sm.pid[t] = f;
    }
    __syncthreads();

    if (tid == 0) {
        int n = 0;
        for (int t = 0; t < T_STEPS; ++t) {
            int p = sm.pid[t];
            if (p == t) { sm.pat_of[t] = n; sm.rep[n] = t; n++; }
            else          sm.pat_of[t] = sm.pat_of[p];
        }
        sm.npat = n;
    }
    __syncthreads();
    const int npat = sm.npat;

    // ---------------- phase 5: per-pattern conv + pool + linear ----------------
    // conv numerics (frozen): taps ascending t4, predicated __fadd_rn chain
    // from 0 == fmaf(w, act∈{0,1}, a) chain; bias last. pool: shfl-max pairs.
    // Two patterns in flight (independent chains) to hide FADD latency.
    for (int p0 = 0; p0 < npat; p0 += PTILE) {
        int ntile = npat - p0; if (ntile > PTILE) ntile = PTILE;

        if (nclass <= 32) {
            int pp = 0;
            for (; pp + 1 < ntile; pp += 2) {
                int tr0 = sm.rep[p0 + pp];
                int tr1 = sm.rep[p0 + pp + 1];
                unsigned s0 = sm.sig[tr0][0];
                unsigned s1 = sm.sig[tr1][0];
                float a0 = 0.0f, a1 = 0.0f;
                #pragma unroll
                for (int t4 = 0; t4 < 16; ++t4) {
                    if (s0 & mask[t4]) a0 = __fadd_rn(a0, wreg[t4]);
                    if (s1 & mask[t4]) a1 = __fadd_rn(a1, wreg[t4]);
                }
                a0 = __fadd_rn(a0, bias_t);
                a1 = __fadd_rn(a1, bias_t);
                float x0 = fmaxf(a0, __shfl_xor_sync(0xFFFFFFFFu, a0, 1));
                float x1 = fmaxf(a1, __shfl_xor_sync(0xFFFFFFFFu, a1, 1));
                float m0 = fmaxf(x0, __shfl_xor_sync(0xFFFFFFFFu, x0, 2));
                float m1 = fmaxf(x1, __shfl_xor_sync(0xFFFFFFFFu, x1, 2));
                if (q == 0) {
                    sm.pooled[pp][pb]     = m0;
                    sm.pooled[pp + 1][pb] = m1;
                }
            }
            if (pp < ntile) {
                int tr = sm.rep[p0 + pp];
                unsigned s0 = sm.sig[tr][0];
                float a = 0.0f;
                #pragma unroll
                for (int t4 = 0; t4 < 16; ++t4)
                    if (s0 & mask[t4]) a = __fadd_rn(a, wreg[t4]);
                a = __fadd_rn(a, bias_t);
                float x = fmaxf(a, __shfl_xor_sync(0xFFFFFFFFu, a, 1));
                float m = fmaxf(x, __shfl_xor_sync(0xFFFFFFFFu, x, 2));
                if (q == 0) sm.pooled[pp][pb] = m;
            }
        } else if (nclass <= 64) {
            int pp = 0;
            for (; pp + 1 < ntile; pp += 2) {
                int tr0 = sm.rep[p0 + pp];
                int tr1 = sm.rep[p0 + pp + 1];
                uint2 sa = *(const uint2*)&sm.sig[tr0][0];
                uint2 sb = *(const uint2*)&sm.sig[tr1][0];
                float a0 = 0.0f, a1 = 0.0f;
                #pragma unroll
                for (int t4 = 0; t4 < 16; ++t4) {
                    unsigned wa = ((wsel >> t4) & 1u) ? sa.y : sa.x;
                    unsigned wb = ((wsel >> t4) & 1u) ? sb.y : sb.x;
                    if (wa & mask[t4]) a0 = __fadd_rn(a0, wreg[t4]);
                    if (wb & mask[t4]) a1 = __fadd_rn(a1, wreg[t4]);
                }
                a0 = __fadd_rn(a0, bias_t);
                a1 = __fadd_rn(a1, bias_t);
                float x0 = fmaxf(a0, __shfl_xor_sync(0xFFFFFFFFu, a0, 1));
                float x1 = fmaxf(a1, __shfl_xor_sync(0xFFFFFFFFu, a1, 1));
                float m0 = fmaxf(x0, __shfl_xor_sync(0xFFFFFFFFu, x0, 2));
                float m1 = fmaxf(x1, __shfl_xor_sync(0xFFFFFFFFu, x1, 2));
                if (q == 0) {
                    sm.pooled[pp][pb]     = m0;
                    sm.pooled[pp + 1][pb] = m1;
                }
            }
            if (pp < ntile) {
                int tr = sm.rep[p0 + pp];
                uint2 sa = *(const uint2*)&sm.sig[tr][0];
                float a = 0.0f;
                #pragma unroll
                for (int t4 = 0; t4 < 16; ++t4) {
                    unsigned wa = ((wsel >> t4) & 1u) ? sa.y : sa.x;
                    if (wa & mask[t4]) a = __fadd_rn(a, wreg[t4]);
                }
                a = __fadd_rn(a, bias_t);
                float x = fmaxf(a, __shfl_xor_sync(0xFFFFFFFFu, a, 1));
                float m = fmaxf(x, __shfl_xor_sync(0xFFFFFFFFu, x, 2));
                if (q == 0) sm.pooled[pp][pb] = m;
            }
        } else {
            for (int pp = 0; pp < ntile; ++pp) {
                int tr = sm.rep[p0 + pp];
                const char* row = (const char*)&sm.sig[tr][0];
                float a = 0.0f;
                #pragma unroll
                for (int t4 = 0; t4 < 16; ++t4) {
                    unsigned off = (woffpack[t4 >> 2] >> ((t4 & 3) << 3)) & 0xFFu;
                    unsigned w = *(const unsigned*)(row + off);
                    if (w & mask[t4]) a = __fadd_rn(a, wreg[t4]);
                }
                a = __fadd_rn(a, bias_t);
                float x = fmaxf(a, __shfl_xor_sync(0xFFFFFFFFu, a, 1));
                float m = fmaxf(x, __shfl_xor_sync(0xFFFFFFFFu, x, 2));
                if (q == 0) sm.pooled[pp][pb] = m;
            }
        }
        __syncthreads();

        // Linear (frozen): cublas sliced1x4 tree — 4 mod-4 partials, 18 serial
        // FMAs each, halving combine (P0+P2)+(P1+P3), bias last.
        for (int idx = tid; idx < ntile * NOUT; idx += NTHREADS) {
            int oo = idx % NOUT;
            int pp = idx / NOUT;
            const float* pv = sm.pooled[pp];
            const float* wv = &sm.wlin[oo * 72];
            float P0 = 0.0f, P1 = 0.0f, P2 = 0.0f, P3 = 0.0f;
            #pragma unroll
            for (int j = 0; j < 18; ++j) {
                int k = j * 4;
                P0 = fmaf(pv[k + 0], wv[k + 0], P0);
                P1 = fmaf(pv[k + 1], wv[k + 1], P1);
                P2 = fmaf(pv[k + 2], wv[k + 2], P2);
                P3 = fmaf(pv[k + 3], wv[k + 3], P3);
            }
            float a02 = __fadd_rn(P0, P2);
            float a13 = __fadd_rn(P1, P3);
            float acc = __fadd_rn(a02, a13);
            sm.lin_pat[p0 + pp][oo] = __fadd_rn(acc, sm.blin[oo]);
        }
        __syncthreads();
    }

    // ---------------- phase 6: fused sequential decoder (frozen) -----------
    if (tid < NOUT) {
        float v = 0.0f, cur = 0.0f, ss = 0.0f;
        float* __restrict__ mem = out + BATCH * NOUT;
        float* __restrict__ spk = mem + (long)T_STEPS * BATCH * NOUT;
        const int base = b * NOUT + tid;
        for (int t = 0; t < T_STEPS; ++t) {
            float lv = sm.lin_pat[sm.pat_of[t]][tid];
            float vd = fmaf(0.1f, __fsub_rn(cur, v), v);
            float id = fmaf(-0.2f, cur, cur);
            bool  sp = vd > 1.0f;
            v   = sp ? 0.0f : vd;
            cur = __fadd_rn(id, lv);
            float spf = sp ? 1.0f : 0.0f;
            ss += spf;
            long ofs = (long)t * (BATCH * NOUT) + base;
            mem[ofs] = v;
            spk[ofs] = spf;
        }
        out[base] = ss;
    }
}

extern "C" void kernel_launch(void* const* d_in, const int* in_sizes, int n_in,
                              void* d_out, int out_size) {
    const float* x      = (const float*)d_in[0];
    const float* conv_w = (const float*)d_in[1];
    const float* conv_b = (const float*)d_in[2];
    const float* lin_w  = (const float*)d_in[3];
    const float* lin_b  = (const float*)d_in[4];
    float* out = (float*)d_out;

    k_periods<<<(BATCH * NPIX + 255) / 256, 256>>>(x);
    k_forward<<<BATCH, NTHREADS>>>(conv_w, conv_b, lin_w, lin_b, out);
}